// round 16
// baseline (speedup 1.0000x reference)
#include <cuda_runtime.h>

#define N_RAYS   8192
#define N_SAMP   256
#define HID      64
#define OUT_ROW  261        // 3 colors + depth + missed + 256 probs
#define RPB      2          // rays per block (one warp per ray)
#define THREADS  64

__device__ __forceinline__ unsigned long long pack2(float lo, float hi) {
    unsigned long long r;
    asm("mov.b64 %0, {%1, %2};" : "=l"(r) : "f"(lo), "f"(hi));
    return r;
}
__device__ __forceinline__ void unpack2(unsigned long long v, float& lo, float& hi) {
    asm("mov.b64 {%0, %1}, %2;" : "=f"(lo), "=f"(hi) : "l"(v));
}
#define FMA2(acc, x, y) asm("fma.rn.f32x2 %0, %1, %2, %0;" : "+l"(acc) : "l"(x), "l"(y))

__device__ __forceinline__ float fast_sigmoid(float x) {
    float th;
    asm("tanh.approx.f32 %0, %1;" : "=f"(th) : "f"(0.5f * x));
    return fmaf(0.5f, th, 0.5f);
}

__global__ void __launch_bounds__(THREADS, 12)
volume_render_kernel(const float* __restrict__ ray_start,
                     const float* __restrict__ ray_dir,
                     const float* __restrict__ depth,
                     const float* __restrict__ dists,
                     const int*   __restrict__ sampled_idx,
                     const float* __restrict__ W1,
                     const float* __restrict__ b1,
                     const float* __restrict__ w_sigma,
                     const float* __restrict__ W_rgb,
                     const float* __restrict__ W_dir,
                     const float* __restrict__ b_rgb,
                     float* __restrict__ out)
{
    __shared__ ulonglong2 sAB[RPB][HID];  // .x=(a,a) .y=(b,b) per ray
    __shared__ ulonglong2 sWa[HID];       // .x=(ws,ws) .y=(wr0,wr0)
    __shared__ ulonglong2 sWb[HID];       // .x=(wr1,wr1) .y=(wr2,wr2)

    const int t    = threadIdx.x;
    const int rl   = t >> 5;      // warp id == ray slot (0..1)
    const int lane = t & 31;
    const int r    = blockIdx.x * RPB + rl;

    const float rs0 = ray_start[3*r+0], rs1 = ray_start[3*r+1], rs2 = ray_start[3*r+2];
    const float rd0 = ray_dir  [3*r+0], rd1 = ray_dir  [3*r+1], rd2 = ray_dir  [3*r+2];

    // ---- prologue: per-ray affine coeffs + splatted weights ----
    #pragma unroll
    for (int q = 0; q < 2; q++) {
        int jj = lane + 32*q;
        float w0 = W1[jj], w1 = W1[HID + jj], w2 = W1[2*HID + jj];
        float a  = fmaf(rs2, w2, fmaf(rs1, w1, fmaf(rs0, w0, b1[jj])));
        float b  = fmaf(rd2, w2, fmaf(rd1, w1, rd0 * w0));
        sAB[rl][jj] = make_ulonglong2(pack2(a, a), pack2(b, b));
    }
    {
        int jj = t;               // 64 threads cover HID exactly
        float ws = w_sigma[jj];
        float q0 = W_rgb[3*jj+0];
        float q1 = W_rgb[3*jj+1];
        float q2 = W_rgb[3*jj+2];
        sWa[jj] = make_ulonglong2(pack2(ws, ws), pack2(q0, q0));
        sWb[jj] = make_ulonglong2(pack2(q1, q1), pack2(q2, q2));
    }

    // per-ray view-dir color offsets — folded into accumulator init
    const float dc0 = fmaf(rd2, W_dir[6], fmaf(rd1, W_dir[3], fmaf(rd0, W_dir[0], b_rgb[0])));
    const float dc1 = fmaf(rd2, W_dir[7], fmaf(rd1, W_dir[4], fmaf(rd0, W_dir[1], b_rgb[1])));
    const float dc2 = fmaf(rd2, W_dir[8], fmaf(rd1, W_dir[5], fmaf(rd0, W_dir[2], b_rgb[2])));
    __syncthreads();

    // ---- load 8 depths per thread ----
    const size_t si = (size_t)r * N_SAMP + lane * 8;
    const float4 dA = *(const float4*)(depth + si);
    const float4 dB = *(const float4*)(depth + si + 4);

    unsigned long long td[4];
    td[0] = pack2(dA.x, dA.y); td[1] = pack2(dA.z, dA.w);
    td[2] = pack2(dB.x, dB.y); td[3] = pack2(dB.z, dB.w);

    unsigned long long sg[4] = {0,0,0,0};
    unsigned long long a0[4], a1[4], a2[4];
    #pragma unroll
    for (int p = 0; p < 4; p++) {
        a0[p] = pack2(dc0, dc0);
        a1[p] = pack2(dc1, dc1);
        a2[p] = pack2(dc2, dc2);
    }

    // ---- software-pipelined MLP loop: prefetch k+1 while computing k ----
    ulonglong2 ab = sAB[rl][0];
    ulonglong2 wa = sWa[0];
    ulonglong2 wb = sWb[0];

    float4 xA, xB;
    int4   iA, iB;

    #pragma unroll
    for (int k = 0; k < HID; k++) {
        // prefetch next k's operands (dead past the last iteration)
        ulonglong2 abn, wan, wbn;
        if (k + 1 < HID) {
            abn = sAB[rl][k+1];
            wan = sWa[k+1];
            wbn = sWb[k+1];
        }
        // hide the epilogue global loads behind the tail of the loop
        if (k == 48) {
            xA = *(const float4*)(dists + si);
            xB = *(const float4*)(dists + si + 4);
            iA = *(const int4*)(sampled_idx + si);
            iB = *(const int4*)(sampled_idx + si + 4);
        }
        #pragma unroll
        for (int p = 0; p < 4; p++) {
            unsigned long long h;
            asm("fma.rn.f32x2 %0, %1, %2, %3;"
                : "=l"(h) : "l"(td[p]), "l"(ab.y), "l"(ab.x));
            float hlo, hhi;
            unpack2(h, hlo, hhi);
            hlo = fmaxf(hlo, 0.f);   // FMNMX — ALU pipe
            hhi = fmaxf(hhi, 0.f);
            unsigned long long pr = pack2(hlo, hhi);
            FMA2(sg[p], pr, wa.x);
            FMA2(a0[p], pr, wa.y);
            FMA2(a1[p], pr, wb.x);
            FMA2(a2[p], pr, wb.y);
        }
        ab = abn; wa = wan; wb = wbn;
    }

    // ---- free energy + local inclusive prefix cum[1..8] ----
    float cum[9];
    cum[0] = 0.f;
    {
        const float ddv[8] = {xA.x,xA.y,xA.z,xA.w,xB.x,xB.y,xB.z,xB.w};
        const int   mkv[8] = {iA.x!=-1,iA.y!=-1,iA.z!=-1,iA.w!=-1,
                              iB.x!=-1,iB.y!=-1,iB.z!=-1,iB.w!=-1};
        #pragma unroll
        for (int p = 0; p < 4; p++) {
            float slo, shi;
            unpack2(sg[p], slo, shi);
            float f0 = mkv[2*p]   ? fmaxf(slo, 0.f) * ddv[2*p]   * 7.0f : 0.f;
            float f1 = mkv[2*p+1] ? fmaxf(shi, 0.f) * ddv[2*p+1] * 7.0f : 0.f;
            cum[2*p+1] = cum[2*p] + f0;
            cum[2*p+2] = cum[2*p+1] + f1;
        }
    }
    const float run = cum[8];

    // warp-exclusive scan of per-thread totals
    float v = run;
    #pragma unroll
    for (int o = 1; o < 32; o <<= 1) {
        float n = __shfl_up_sync(0xffffffffu, v, o);
        if (lane >= o) v += n;
    }
    const float excl = v - run;

    float* orow = out + (size_t)r * OUT_ROW;

    // ---- telescoping transmittance: prob[k] = E[k] - E[k+1] ----
    float Ep = __expf(-excl);
    const float Efirst = Ep;
    float s1 = 0.f, s2 = 0.f, s3 = 0.f, s4 = 0.f;
    #pragma unroll
    for (int p = 0; p < 4; p++) {
        float t0, t1;
        unpack2(td[p], t0, t1);
        float c00, c01; unpack2(a0[p], c00, c01);
        float c10, c11; unpack2(a1[p], c10, c11);
        float c20, c21; unpack2(a2[p], c20, c21);
        #pragma unroll
        for (int q = 0; q < 2; q++) {
            int k = 2*p + q;
            float Ek   = __expf(-(excl + cum[k+1]));
            float prob = Ep - Ek;
            Ep = Ek;
            float rr = fast_sigmoid(q ? c01 : c00);
            float gg = fast_sigmoid(q ? c11 : c10);
            float bb = fast_sigmoid(q ? c21 : c20);
            orow[5 + 8*lane + k] = prob;
            s1 = fmaf(q ? t1 : t0, prob, s1);
            s2 = fmaf(rr, prob, s2);
            s3 = fmaf(gg, prob, s3);
            s4 = fmaf(bb, prob, s4);
        }
    }
    float s0 = Efirst - Ep;   // sum of probs telescopes

    #pragma unroll
    for (int o = 16; o; o >>= 1) {
        s0 += __shfl_xor_sync(0xffffffffu, s0, o);
        s1 += __shfl_xor_sync(0xffffffffu, s1, o);
        s2 += __shfl_xor_sync(0xffffffffu, s2, o);
        s3 += __shfl_xor_sync(0xffffffffu, s3, o);
        s4 += __shfl_xor_sync(0xffffffffu, s4, o);
    }
    if (lane == 0) {
        orow[0] = s2;        // color r
        orow[1] = s3;        // color g
        orow[2] = s4;        // color b
        orow[3] = s1;        // depth
        orow[4] = 1.f - s0;  // missed
    }
}

extern "C" void kernel_launch(void* const* d_in, const int* in_sizes, int n_in,
                              void* d_out, int out_size)
{
    const float* ray_start = (const float*)d_in[0];
    const float* ray_dir   = (const float*)d_in[1];
    const float* depth     = (const float*)d_in[2];
    const float* dists     = (const float*)d_in[3];
    const int*   sidx      = (const int*)d_in[4];
    const float* W1        = (const float*)d_in[5];
    const float* b1        = (const float*)d_in[6];
    const float* w_sigma   = (const float*)d_in[7];
    const float* W_rgb     = (const float*)d_in[8];
    const float* W_dir     = (const float*)d_in[9];
    const float* b_rgb     = (const float*)d_in[10];
    float* out = (float*)d_out;

    volume_render_kernel<<<N_RAYS / RPB, THREADS>>>(
        ray_start, ray_dir, depth, dists, sidx,
        W1, b1, w_sigma, W_rgb, W_dir, b_rgb, out);
}

// round 17
// speedup vs baseline: 1.4536x; 1.4536x over previous
#include <cuda_runtime.h>

#define N_RAYS   8192
#define N_SAMP   256
#define HID      64
#define OUT_ROW  261        // 3 colors + depth + missed + 256 probs
#define RPB      2          // rays per block (one warp per ray)
#define THREADS  64
#define FULLM    0xffffffffu

__device__ __forceinline__ float fast_sigmoid(float x) {
    float th;
    asm("tanh.approx.f32 %0, %1;" : "=f"(th) : "f"(0.5f * x));
    return fmaf(0.5f, th, 0.5f);
}
__device__ __forceinline__ float4 f4add(float4 a, float4 b) {
    return make_float4(a.x+b.x, a.y+b.y, a.z+b.z, a.w+b.w);
}
__device__ __forceinline__ float4 f4sub(float4 a, float4 b) {
    return make_float4(a.x-b.x, a.y-b.y, a.z-b.z, a.w-b.w);
}
__device__ __forceinline__ float4 f4scale(float4 a, float s) {
    return make_float4(a.x*s, a.y*s, a.z*s, a.w*s);
}

#define SCAN_ONE(v)                                                   \
    { _Pragma("unroll")                                               \
      for (int o_ = 1; o_ < 32; o_ <<= 1) {                           \
          float n_ = __shfl_up_sync(FULLM, (v), o_);                  \
          if (lane >= o_) (v) += n_;                                  \
      } }

#define BF_ONE(v)                                                     \
    { _Pragma("unroll")                                               \
      for (int o_ = 16; o_; o_ >>= 1)                                 \
          (v) += __shfl_xor_sync(FULLM, (v), o_); }

__global__ void __launch_bounds__(THREADS, 12)
volume_render_kernel(const float* __restrict__ ray_start,
                     const float* __restrict__ ray_dir,
                     const float* __restrict__ depth,
                     const float* __restrict__ dists,
                     const int*   __restrict__ sampled_idx,
                     const float* __restrict__ W1,
                     const float* __restrict__ b1,
                     const float* __restrict__ w_sigma,
                     const float* __restrict__ W_rgb,
                     const float* __restrict__ W_dir,
                     const float* __restrict__ b_rgb,
                     float* __restrict__ out)
{
    __shared__ float  sTun[RPB][HID];       // unsorted breakpoints
    __shared__ float  sTs [RPB][HID];       // sorted breakpoints
    __shared__ float4 sdA [RPB][HID];       // sorted deltas (A = w*a part)
    __shared__ float4 sdB [RPB][HID];       // sorted deltas (B = w*b part)
    __shared__ float4 tabA[RPB][HID + 1];   // prefix table: SA per segment
    __shared__ float4 tabB[RPB][HID + 1];   // prefix table: SB per segment

    const int t    = threadIdx.x;
    const int rl   = t >> 5;
    const int lane = t & 31;
    const int r    = blockIdx.x * RPB + rl;

    const float rs0 = ray_start[3*r+0], rs1 = ray_start[3*r+1], rs2 = ray_start[3*r+2];
    const float rd0 = ray_dir  [3*r+0], rd1 = ray_dir  [3*r+1], rd2 = ray_dir  [3*r+2];

    // ---- early global loads (consumed much later) ----
    const size_t si = (size_t)r * N_SAMP + lane * 8;
    const float4 dAq = *(const float4*)(depth + si);
    const float4 dBq = *(const float4*)(depth + si + 4);
    const float4 xAq = *(const float4*)(dists + si);
    const float4 xBq = *(const float4*)(dists + si + 4);
    const int4   iAq = *(const int4*)(sampled_idx + si);
    const int4   iBq = *(const int4*)(sampled_idx + si + 4);

    // ---- per-unit: a, b, weighted deltas, breakpoint ----
    float4 baseA = make_float4(0.f,0.f,0.f,0.f);
    float4 baseB = make_float4(0.f,0.f,0.f,0.f);
    float4 delA[2], delB[2];
    float  tst[2];
    #pragma unroll
    for (int hh = 0; hh < 2; hh++) {
        const int j = lane + 32*hh;
        float w0 = W1[j], w1 = W1[HID + j], w2 = W1[2*HID + j];
        float a  = fmaf(rs2, w2, fmaf(rs1, w1, fmaf(rs0, w0, b1[j])));
        float b  = fmaf(rd2, w2, fmaf(rd1, w1, rd0 * w0));
        float ws = w_sigma[j];
        float q0 = W_rgb[3*j+0], q1 = W_rgb[3*j+1], q2 = W_rgb[3*j+2];
        float4 wa = make_float4(ws*a, q0*a, q1*a, q2*a);
        float4 wb = make_float4(ws*b, q0*b, q1*b, q2*b);
        float tstar, sgn;
        if (b != 0.f) {
            tstar = __fdividef(-a, b);
            sgn   = (b > 0.f) ? 1.f : -1.f;
            if (b < 0.f) {           // active as t -> -inf
                baseA = f4add(baseA, wa);
                baseB = f4add(baseB, wb);
            }
        } else {
            tstar = __int_as_float(0x7f800000);  // +inf: never crosses
            sgn   = 0.f;
            if (a > 0.f) {           // constant-active unit (wb = 0)
                baseA = f4add(baseA, wa);
                baseB = f4add(baseB, wb);
            }
        }
        delA[hh] = f4scale(wa, sgn);
        delB[hh] = f4scale(wb, sgn);
        tst[hh]  = tstar;
        sTun[rl][j] = tstar;
    }
    __syncwarp();

    // ---- rank each breakpoint (all-pairs count, broadcast LDS) ----
    int rk0 = 0, rk1 = 0;
    for (int k = 0; k < HID; k++) {
        float tk = sTun[rl][k];
        rk0 += (tk < tst[0]) || (tk == tst[0] && k < lane);
        rk1 += (tk < tst[1]) || (tk == tst[1] && k < lane + 32);
    }
    sTs[rl][rk0] = tst[0]; sdA[rl][rk0] = delA[0]; sdB[rl][rk0] = delB[0];
    sTs[rl][rk1] = tst[1]; sdA[rl][rk1] = delA[1]; sdB[rl][rk1] = delB[1];

    // ---- reduce init across lanes; fold view-dir offsets into rgb comps ----
    BF_ONE(baseA.x) BF_ONE(baseA.y) BF_ONE(baseA.z) BF_ONE(baseA.w)
    BF_ONE(baseB.x) BF_ONE(baseB.y) BF_ONE(baseB.z) BF_ONE(baseB.w)
    const float dc0 = fmaf(rd2, W_dir[6], fmaf(rd1, W_dir[3], fmaf(rd0, W_dir[0], b_rgb[0])));
    const float dc1 = fmaf(rd2, W_dir[7], fmaf(rd1, W_dir[4], fmaf(rd0, W_dir[1], b_rgb[1])));
    const float dc2 = fmaf(rd2, W_dir[8], fmaf(rd1, W_dir[5], fmaf(rd0, W_dir[2], b_rgb[2])));
    baseA.y += dc0; baseA.z += dc1; baseA.w += dc2;

    __syncwarp();

    // ---- scan sorted deltas -> 65-row segment table ----
    float4 A0 = sdA[rl][2*lane], A1 = sdA[rl][2*lane+1];
    float4 B0 = sdB[rl][2*lane], B1 = sdB[rl][2*lane+1];
    float4 psA = f4add(A0, A1), psB = f4add(B0, B1);
    SCAN_ONE(psA.x) SCAN_ONE(psA.y) SCAN_ONE(psA.z) SCAN_ONE(psA.w)
    SCAN_ONE(psB.x) SCAN_ONE(psB.y) SCAN_ONE(psB.z) SCAN_ONE(psB.w)
    float4 rowA2 = f4add(baseA, psA);        // table[2l+2]
    float4 rowB2 = f4add(baseB, psB);
    tabA[rl][2*lane+1] = f4sub(rowA2, A1);   // table[2l+1]
    tabB[rl][2*lane+1] = f4sub(rowB2, B1);
    tabA[rl][2*lane+2] = rowA2;
    tabB[rl][2*lane+2] = rowB2;
    if (lane == 0) { tabA[rl][0] = baseA; tabB[rl][0] = baseB; }
    __syncwarp();

    // ---- per sample: binary search + 4 FMA evaluation ----
    const float tdv[8] = {dAq.x,dAq.y,dAq.z,dAq.w,dBq.x,dBq.y,dBq.z,dBq.w};
    float sgv[8], c0v[8], c1v[8], c2v[8];
    #pragma unroll
    for (int k = 0; k < 8; k++) {
        const float tt = tdv[k];
        int kk = 0;
        #pragma unroll
        for (int s = 32; s >= 1; s >>= 1)
            if (sTs[rl][kk + s - 1] < tt) kk += s;   // kk <= 63
        if (sTs[rl][kk] < tt) kk++;                  // count in [0,64]
        float4 SA = tabA[rl][kk];
        float4 SB = tabB[rl][kk];
        sgv[k] = fmaf(SB.x, tt, SA.x);
        c0v[k] = fmaf(SB.y, tt, SA.y);
        c1v[k] = fmaf(SB.z, tt, SA.z);
        c2v[k] = fmaf(SB.w, tt, SA.w);
    }

    // ---- free energy + local inclusive prefix ----
    const float ddv[8] = {xAq.x,xAq.y,xAq.z,xAq.w,xBq.x,xBq.y,xBq.z,xBq.w};
    const int   mkv[8] = {iAq.x!=-1,iAq.y!=-1,iAq.z!=-1,iAq.w!=-1,
                          iBq.x!=-1,iBq.y!=-1,iBq.z!=-1,iBq.w!=-1};
    float cum[9];
    cum[0] = 0.f;
    #pragma unroll
    for (int k = 0; k < 8; k++) {
        float fe = mkv[k] ? fmaxf(sgv[k], 0.f) * ddv[k] * 7.0f : 0.f;
        cum[k+1] = cum[k] + fe;
    }
    const float run = cum[8];

    // warp-exclusive scan of per-thread totals
    float v = run;
    #pragma unroll
    for (int o = 1; o < 32; o <<= 1) {
        float n = __shfl_up_sync(FULLM, v, o);
        if (lane >= o) v += n;
    }
    const float excl = v - run;

    float* orow = out + (size_t)r * OUT_ROW;

    // ---- telescoping transmittance: prob[k] = E[k] - E[k+1] ----
    float Ep = __expf(-excl);
    const float Efirst = Ep;
    float s1 = 0.f, s2 = 0.f, s3 = 0.f, s4 = 0.f;
    #pragma unroll
    for (int k = 0; k < 8; k++) {
        float Ek   = __expf(-(excl + cum[k+1]));
        float prob = Ep - Ek;
        Ep = Ek;
        float rr = fast_sigmoid(c0v[k]);
        float gg = fast_sigmoid(c1v[k]);
        float bb = fast_sigmoid(c2v[k]);
        orow[5 + 8*lane + k] = prob;
        s1 = fmaf(tdv[k], prob, s1);
        s2 = fmaf(rr, prob, s2);
        s3 = fmaf(gg, prob, s3);
        s4 = fmaf(bb, prob, s4);
    }
    float s0 = Efirst - Ep;   // sum of probs telescopes

    #pragma unroll
    for (int o = 16; o; o >>= 1) {
        s0 += __shfl_xor_sync(FULLM, s0, o);
        s1 += __shfl_xor_sync(FULLM, s1, o);
        s2 += __shfl_xor_sync(FULLM, s2, o);
        s3 += __shfl_xor_sync(FULLM, s3, o);
        s4 += __shfl_xor_sync(FULLM, s4, o);
    }
    if (lane == 0) {
        orow[0] = s2;        // color r
        orow[1] = s3;        // color g
        orow[2] = s4;        // color b
        orow[3] = s1;        // depth
        orow[4] = 1.f - s0;  // missed
    }
}

extern "C" void kernel_launch(void* const* d_in, const int* in_sizes, int n_in,
                              void* d_out, int out_size)
{
    const float* ray_start = (const float*)d_in[0];
    const float* ray_dir   = (const float*)d_in[1];
    const float* depth     = (const float*)d_in[2];
    const float* dists     = (const float*)d_in[3];
    const int*   sidx      = (const int*)d_in[4];
    const float* W1        = (const float*)d_in[5];
    const float* b1        = (const float*)d_in[6];
    const float* w_sigma   = (const float*)d_in[7];
    const float* W_rgb     = (const float*)d_in[8];
    const float* W_dir     = (const float*)d_in[9];
    const float* b_rgb     = (const float*)d_in[10];
    float* out = (float*)d_out;

    volume_render_kernel<<<N_RAYS / RPB, THREADS>>>(
        ray_start, ray_dir, depth, dists, sidx,
        W1, b1, w_sigma, W_rgb, W_dir, b_rgb, out);
}